// round 15
// baseline (speedup 1.0000x reference)
#include <cuda_runtime.h>
#include <cuda_bf16.h>
#include <cstdint>

// ---------------- problem geometry ----------------
#define T_TOK   4096
#define D_MODEL 4096
#define H_HEADS 32
#define DHEAD   128
#define B_SEQ   4
#define SQ      1024
#define HIST    1024
#define SKV     2048
#define NBLK    32
#define BS_PAGE 64
#define ATT_SCALE  0.08838834764831845f
#define INV_LN1024 0.14426950408889634f

// ---------------- scratch ----------------
__device__ float g_qkv[50331648];            // [T, 3*D]
__device__ float g_attn[16777216];           // [T, D] (tf32-rounded by flash)
__device__ float g_hidR[16777216];           // [T, D] tf32-rounded hidden
__device__ float g_wqkvT[50331648];          // [3D, D] tf32-rounded, transposed
__device__ float g_wprojT[16777216];         // [D, D]
__device__ __nv_bfloat16 g_kh[33554432];     // [B,H,SKV,DH] hi
__device__ __nv_bfloat16 g_kl[33554432];     // lo
__device__ __nv_bfloat16 g_vh[33554432];
__device__ __nv_bfloat16 g_vl[33554432];

// ---------------- helpers ----------------
__device__ __forceinline__ uint32_t smem_u32(const void* p) {
    uint32_t a;
    asm("{ .reg .u64 t; cvta.to.shared.u64 t, %1; cvt.u32.u64 %0, t; }"
        : "=r"(a) : "l"(p));
    return a;
}
__device__ __forceinline__ uint32_t f2tf32(float f) {
    uint32_t u;
    asm("cvt.rna.tf32.f32 %0, %1;" : "=r"(u) : "f"(f));
    return u;
}
__device__ __forceinline__ uint32_t pack2(__nv_bfloat16 a, __nv_bfloat16 b) {
    __nv_bfloat162 t = __nv_bfloat162(a, b);   // a -> low 16 bits (k even)
    return *reinterpret_cast<uint32_t*>(&t);
}
__device__ __forceinline__ void split_bf16(float f, __nv_bfloat16& h, __nv_bfloat16& l) {
    h = __float2bfloat16(f);
    l = __float2bfloat16(f - __bfloat162float(h));
}
#define CP_ASYNC16(dst, src) \
    asm volatile("cp.async.ca.shared.global [%0], [%1], 16;" \
                 :: "r"(dst), "l"(src) : "memory")
#define CP_COMMIT() asm volatile("cp.async.commit_group;" ::: "memory")
#define CP_WAIT(n)  asm volatile("cp.async.wait_group %0;" :: "n"(n) : "memory")
#define LDSM_X4(R0,R1,R2,R3,A) \
    asm volatile("ldmatrix.sync.aligned.m8n8.x4.shared.b16 {%0,%1,%2,%3}, [%4];" \
                 : "=r"(R0), "=r"(R1), "=r"(R2), "=r"(R3) : "r"(A))
#define LDSM_X4_T(R0,R1,R2,R3,A) \
    asm volatile("ldmatrix.sync.aligned.m8n8.x4.trans.shared.b16 {%0,%1,%2,%3}, [%4];" \
                 : "=r"(R0), "=r"(R1), "=r"(R2), "=r"(R3) : "r"(A))
__device__ __forceinline__ void mma_bf16(float* c, const uint32_t* a, const uint32_t* b) {
    asm volatile(
        "mma.sync.aligned.m16n8k16.row.col.f32.bf16.bf16.f32 "
        "{%0,%1,%2,%3}, {%4,%5,%6,%7}, {%8,%9}, {%0,%1,%2,%3};"
        : "+f"(c[0]), "+f"(c[1]), "+f"(c[2]), "+f"(c[3])
        : "r"(a[0]), "r"(a[1]), "r"(a[2]), "r"(a[3]), "r"(b[0]), "r"(b[1]));
}
__device__ __forceinline__ void mma_tf32(float* c, const uint32_t* a, const uint32_t* b) {
    asm volatile(
        "mma.sync.aligned.m16n8k8.row.col.f32.tf32.tf32.f32 "
        "{%0,%1,%2,%3}, {%4,%5,%6,%7}, {%8,%9}, {%0,%1,%2,%3};"
        : "+f"(c[0]), "+f"(c[1]), "+f"(c[2]), "+f"(c[3])
        : "r"(a[0]), "r"(a[1]), "r"(a[2]), "r"(a[3]), "r"(b[0]), "r"(b[1]));
}
// exp(x) for x <= 0, FMA-pipe only. ~1e-7 rel err.
__device__ __forceinline__ float fast_exp(float x) {
    float y = fmaxf(x * 1.4426950408889634f, -126.f);
    float z = __fadd_rn(y, 12582912.f);
    int   n = __float_as_int(z) - 0x4B400000;
    float f = y - __fsub_rn(z, 12582912.f);
    float t = f * 0.6931471805599453f;
    float p = __fmaf_rn(t, 0.0013888889f, 0.0083333333f);
    p = __fmaf_rn(t, p, 0.0416666667f);
    p = __fmaf_rn(t, p, 0.1666666667f);
    p = __fmaf_rn(t, p, 0.5f);
    p = __fmaf_rn(t, p, 1.0f);
    p = __fmaf_rn(t, p, 1.0f);
    return p * __int_as_float((n + 127) << 23);
}

// =====================================================================
// Prep: W[K][N] fp32 -> WT[N][K] fp32 with tf32(RNA) rounding applied.
// =====================================================================
__global__ __launch_bounds__(256) void transpose_tf32_kernel(
    const float* __restrict__ W, float* __restrict__ WT, int Kd, int Nd)
{
    __shared__ float ts[32][33];
    const int n0 = blockIdx.x * 32, k0 = blockIdx.y * 32;
    const int tx = threadIdx.x, ty = threadIdx.y;
    #pragma unroll
    for (int j = ty; j < 32; j += 8)
        ts[j][tx] = W[(size_t)(k0 + j) * Nd + n0 + tx];
    __syncthreads();
    #pragma unroll
    for (int j = ty; j < 32; j += 8)
        WT[(size_t)(n0 + j) * Kd + k0 + tx] = __uint_as_float(f2tf32(ts[tx][j]));
}

// =====================================================================
// Prep: elementwise tf32(RNA) round.
// =====================================================================
__global__ __launch_bounds__(256) void round_tf32_kernel(
    const float* __restrict__ X, float* __restrict__ Y)
{
    const int i = (blockIdx.x * 256 + threadIdx.x) * 4;
    const float4 v = *(const float4*)(X + i);
    uint4 u;
    u.x = f2tf32(v.x); u.y = f2tf32(v.y); u.z = f2tf32(v.z); u.w = f2tf32(v.w);
    *(uint4*)(Y + i) = u;
}

// =====================================================================
// TF32 GEMM, cp.async double-buffered + CTA swizzle (exact R13).
// =====================================================================
#define G_SMEM_BYTES (18432 * 4)

__global__ __launch_bounds__(256, 2) void tf32_gemm_cp_kernel(
    const float* __restrict__ A, const float* __restrict__ BT,
    const float* __restrict__ bias, float* __restrict__ C,
    int M, int N, int K)
{
    extern __shared__ uint32_t sg[];
    const uint32_t sbase = smem_u32(sg);

    const int tid  = threadIdx.x;
    const int lin  = blockIdx.y * gridDim.x + blockIdx.x;
    const int grpW = 8 * gridDim.y;
    const int grp  = lin / grpW;
    const int rem  = lin - grp * grpW;
    const int bcol = grp * 8 + (rem & 7);
    const int brow = rem >> 3;

    const int warp = tid >> 5, lane = tid & 31;
    const int wr = warp >> 2, wc = warp & 3;
    const int gp = lane >> 2, q = lane & 3;
    const int tr = lane & 7, lg = lane >> 3;
    const int row_off = (lg & 2) ? 8 : 0;
    const int col_off = (lg & 1) ? 4 : 0;

    float acc[4][4][4];
    #pragma unroll
    for (int mt = 0; mt < 4; mt++)
        #pragma unroll
        for (int nt = 0; nt < 4; nt++)
            #pragma unroll
            for (int r = 0; r < 4; r++) acc[mt][nt][r] = 0.f;

    const float* Ab = A  + (size_t)(brow * 128) * K;
    const float* Bb = BT + (size_t)(bcol * 128) * K;

    const int fr = tid >> 3, fk = (tid & 7) << 2;

    auto fill = [&](int st, int kt) {
        const uint32_t aoff = sbase + (st * 4608) * 4;
        const uint32_t boff = sbase + ((9216 + st * 4608)) * 4;
        #pragma unroll
        for (int i = 0; i < 4; i++) {
            const int r = fr + 32 * i;
            const uint32_t d = (r * 36 + fk) * 4;
            CP_ASYNC16(aoff + d, Ab + (size_t)r * K + kt + fk);
            CP_ASYNC16(boff + d, Bb + (size_t)r * K + kt + fk);
        }
        CP_COMMIT();
    };

    fill(0, 0);

    for (int kt = 0; kt < K; kt += 32) {
        const int buf = (kt >> 5) & 1;
        const bool more = (kt + 32 < K);
        if (more) { fill(buf ^ 1, kt + 32); CP_WAIT(1); }
        else      { CP_WAIT(0); }
        __syncthreads();

        const uint32_t aoff = sbase + (buf * 4608) * 4;
        const uint32_t boff = sbase + ((9216 + buf * 4608)) * 4;
        #pragma unroll
        for (int kk = 0; kk < 32; kk += 8) {
            uint32_t af[4][4], bf[4][2];
            #pragma unroll
            for (int mt = 0; mt < 4; mt++) {
                const int r = wr * 64 + mt * 16;
                const uint32_t a = aoff + ((r + tr + row_off) * 36 + kk + col_off) * 4;
                uint32_t r0, r1, r2, r3;
                LDSM_X4(r0, r1, r2, r3, a);
                af[mt][0] = r0; af[mt][1] = r2; af[mt][2] = r1; af[mt][3] = r3;
            }
            #pragma unroll
            for (int pp = 0; pp < 2; pp++) {
                const int c0 = wc * 32 + pp * 16;
                const uint32_t a = boff + ((c0 + tr + row_off) * 36 + kk + col_off) * 4;
                uint32_t r0, r1, r2, r3;
                LDSM_X4(r0, r1, r2, r3, a);
                bf[2*pp][0]   = r0; bf[2*pp][1]   = r1;
                bf[2*pp+1][0] = r2; bf[2*pp+1][1] = r3;
            }
            #pragma unroll
            for (int mt = 0; mt < 4; mt++)
                #pragma unroll
                for (int nt = 0; nt < 4; nt++)
                    mma_tf32(acc[mt][nt], af[mt], bf[nt]);
        }
        __syncthreads();
    }

    #pragma unroll
    for (int mt = 0; mt < 4; mt++) {
        const int r0 = brow * 128 + wr * 64 + mt * 16 + gp;
        #pragma unroll
        for (int nt = 0; nt < 4; nt++) {
            const int c0 = bcol * 128 + wc * 32 + nt * 8 + 2 * q;
            float bb0 = 0.f, bb1 = 0.f;
            if (bias) { bb0 = bias[c0]; bb1 = bias[c0 + 1]; }
            float2 v0, v1;
            v0.x = acc[mt][nt][0] + bb0; v0.y = acc[mt][nt][1] + bb1;
            v1.x = acc[mt][nt][2] + bb0; v1.y = acc[mt][nt][3] + bb1;
            *(float2*)&C[(size_t)r0 * N + c0]       = v0;
            *(float2*)&C[(size_t)(r0 + 8) * N + c0] = v1;
        }
    }
}

// =====================================================================
// Build K/V as bf16 hi/lo, [B,H,SKV,DH].  grid (SKV, B), block 128.
// =====================================================================
__global__ void build_kv_kernel(const float* __restrict__ qkv,
                                const float* __restrict__ kcache,
                                const float* __restrict__ vcache,
                                const int* __restrict__ blockOff,
                                const float* __restrict__ cosT,
                                const float* __restrict__ sinT,
                                __nv_bfloat16* __restrict__ Kh,
                                __nv_bfloat16* __restrict__ Kl,
                                __nv_bfloat16* __restrict__ Vh,
                                __nv_bfloat16* __restrict__ Vl)
{
    const int s = blockIdx.x, b = blockIdx.y, d = threadIdx.x;
    if (s < HIST) {
        const int blk = blockOff[b * NBLK + (s >> 6)];
        const size_t src = ((size_t)(blk * BS_PAGE + (s & 63))) * H_HEADS * DHEAD;
        for (int h = 0; h < H_HEADS; h++) {
            const size_t dst = (((size_t)(b * H_HEADS + h)) * SKV + s) * DHEAD + d;
            __nv_bfloat16 hh, ll;
            split_bf16(kcache[src + h * DHEAD + d], hh, ll);
            Kh[dst] = hh; Kl[dst] = ll;
            split_bf16(vcache[src + h * DHEAD + d], hh, ll);
            Vh[dst] = hh; Vl[dst] = ll;
        }
    } else {
        const int t = b * SQ + (s - HIST);
        const int pos = s;
        const float c  = cosT[(size_t)pos * DHEAD + d];
        const float sn = sinT[(size_t)pos * DHEAD + d];
        const float* kp = qkv + (size_t)t * (3 * D_MODEL) + D_MODEL;
        const float* vp = kp + D_MODEL;
        for (int h = 0; h < H_HEADS; h++) {
            const float k1 = kp[h * DHEAD + d];
            const float rot = (d < 64) ? -kp[h * DHEAD + d + 64]
                                       :  kp[h * DHEAD + d - 64];
            const size_t dst = (((size_t)(b * H_HEADS + h)) * SKV + s) * DHEAD + d;
            __nv_bfloat16 hh, ll;
            split_bf16(k1 * c + rot * sn, hh, ll);
            Kh[dst] = hh; Kl[dst] = ll;
            split_bf16(vp[h * DHEAD + d], hh, ll);
            Vh[dst] = hh; Vl[dst] = ll;
        }
    }
}

// =====================================================================
// Flash attention v4: bf16x3, ldmatrix fragments, pre-split K/V,
// PIPELINED cp.async fills.  CTA: 512 threads, q-tile 128.
// GRID TRANSPOSED for K/V L2 residency: x = q-tile (8), y = bh (128);
// a dispatch wave covers all q-tiles of ~18 bh groups (36MB << L2),
// so each bh's K/V is read from DRAM once, not 8 times.
// =====================================================================
#define FL_QH 0
#define FL_QL 8704
#define FL_KH 17408
#define FL_KL 21760
#define FL_VH 26112
#define FL_VL 30464
#define FL_SF 34816
#define FL_PH 43520
#define FL_PL 48128
#define FL_ST 52736
#define FL_SMEM_BYTES (53120 * 4)

__global__ __launch_bounds__(512) void flash_v4_kernel(
    const float* __restrict__ Qg,
    const __nv_bfloat16* __restrict__ Kh,
    const __nv_bfloat16* __restrict__ Kl,
    const __nv_bfloat16* __restrict__ Vh,
    const __nv_bfloat16* __restrict__ Vl,
    const float* __restrict__ cosT,
    const float* __restrict__ sinT,
    float* __restrict__ Og)
{
    extern __shared__ uint32_t fsm[];
    uint32_t* QH = fsm + FL_QH;
    uint32_t* QL = fsm + FL_QL;
    float*    SF = (float*)(fsm + FL_SF);
    uint32_t* PH = fsm + FL_PH;
    uint32_t* PL = fsm + FL_PL;
    float* m_s = (float*)(fsm + FL_ST);
    float* l_s = m_s + 128;
    float* c_s = l_s + 128;
    const uint32_t sbase = smem_u32(fsm);

    const int bh = blockIdx.y;                   // TRANSPOSED grid
    const int b = bh >> 5, h = bh & 31;
    const int q0 = blockIdx.x * 128;             // TRANSPOSED grid
    const int tid = threadIdx.x;
    const int warp = tid >> 5, lane = tid & 31;
    const int gp = lane >> 2, q = lane & 3;
    const int tr = lane & 7, lg = lane >> 3;
    const int wr = warp >> 2, wc = warp & 3;     // S phase: 4x4
    const int wor = warp >> 1, woc = warp & 1;   // PV phase: 8x2
    const int row_off = (lg & 2) ? 8 : 0;        // non-trans grouping
    const int col_off = (lg & 1) ? 4 : 0;
    const int row_off_t = (lg & 1) ? 8 : 0;      // trans grouping
    const int col_off_t = (lg & 2) ? 4 : 0;

    const size_t bhofs = (size_t)bh * SKV * DHEAD;
    const int ntiles = (HIST + q0 + 128) / 64;

    // per-thread fill coordinates (one 64-row tile = 8 cp.async per thread)
    const int frow = tid >> 3;
    const int fc8  = (tid & 7) * 8;
    const uint32_t fdrow = (frow * 68 + fc8) * 4;

    auto issue_K = [&](int s0) {
        const size_t src = bhofs + (size_t)(s0 + frow) * DHEAD + fc8 * 2;
        CP_ASYNC16(sbase + (FL_KH) * 4 + fdrow,      Kh + src);
        CP_ASYNC16(sbase + (FL_KH + 4) * 4 + fdrow,  Kh + src + 8);
        CP_ASYNC16(sbase + (FL_KL) * 4 + fdrow,      Kl + src);
        CP_ASYNC16(sbase + (FL_KL + 4) * 4 + fdrow,  Kl + src + 8);
        CP_COMMIT();
    };
    auto issue_V = [&](int s0) {
        const size_t src = bhofs + (size_t)(s0 + frow) * DHEAD + fc8 * 2;
        CP_ASYNC16(sbase + (FL_VH) * 4 + fdrow,      Vh + src);
        CP_ASYNC16(sbase + (FL_VH + 4) * 4 + fdrow,  Vh + src + 8);
        CP_ASYNC16(sbase + (FL_VL) * 4 + fdrow,      Vl + src);
        CP_ASYNC16(sbase + (FL_VL + 4) * 4 + fdrow,  Vl + src + 8);
        CP_COMMIT();
    };

    // kick off tile-0 fills; they overlap the Q RoPE staging below
    issue_K(0);
    issue_V(0);

    // ---- load Q tile + RoPE + logn + bf16 split ----
    {
        const int row = tid >> 2;
        const int d0  = (tid & 3) * 16;
        const int t   = b * SQ + q0 + row;
        const int pos = HIST + q0 + row;
        const float logn = logf((float)(pos + 1)) * INV_LN1024;
        const float* qrow = Qg + (size_t)t * (3 * D_MODEL) + h * DHEAD;
        const float* crow = cosT + (size_t)pos * DHEAD;
        const float* srow = sinT + (size_t)pos * DHEAD;
        float qa[16], qb[16], ca[16], cb[16], sa[16], sb[16];
        #pragma unroll
        for (int i = 0; i < 4; i++) {
            *(float4*)&qa[4*i] = *(const float4*)(qrow + d0 + 4*i);
            *(float4*)&qb[4*i] = *(const float4*)(qrow + d0 + 64 + 4*i);
            *(float4*)&ca[4*i] = *(const float4*)(crow + d0 + 4*i);
            *(float4*)&cb[4*i] = *(const float4*)(crow + d0 + 64 + 4*i);
            *(float4*)&sa[4*i] = *(const float4*)(srow + d0 + 4*i);
            *(float4*)&sb[4*i] = *(const float4*)(srow + d0 + 64 + 4*i);
        }
        #pragma unroll
        for (int j = 0; j < 8; j++) {
            float f0 = (qa[2*j]   * ca[2*j]   - qb[2*j]   * sa[2*j])   * logn;
            float f1 = (qa[2*j+1] * ca[2*j+1] - qb[2*j+1] * sa[2*j+1]) * logn;
            float g0 = (qb[2*j]   * cb[2*j]   + qa[2*j]   * sb[2*j])   * logn;
            float g1 = (qb[2*j+1] * cb[2*j+1] + qa[2*j+1] * sb[2*j+1]) * logn;
            __nv_bfloat16 h0, l0, h1, l1;
            split_bf16(f0, h0, l0); split_bf16(f1, h1, l1);
            QH[row * 68 + d0/2 + j] = pack2(h0, h1);
            QL[row * 68 + d0/2 + j] = pack2(l0, l1);
            split_bf16(g0, h0, l0); split_bf16(g1, h1, l1);
            QH[row * 68 + (d0 + 64)/2 + j] = pack2(h0, h1);
            QL[row * 68 + (d0 + 64)/2 + j] = pack2(l0, l1);
        }
    }
    if (tid < 128) { m_s[tid] = -1e30f; l_s[tid] = 0.f; }

    float oacc[8][4];
    #pragma unroll
    for (int nt = 0; nt < 8; nt++)
        { oacc[nt][0]=0.f; oacc[nt][1]=0.f; oacc[nt][2]=0.f; oacc[nt][3]=0.f; }

    __syncthreads();

    for (int kt = 0; kt < ntiles; kt++) {
        const int s0 = kt * 64;
        const bool more = (kt + 1 < ntiles);

        // K[kt] ready (V[kt] may still be in flight: groups drain in order)
        CP_WAIT(1);
        __syncthreads();

        // ---- S = Q @ K^T  (bf16x3, ldmatrix) ----
        float sacc[2][2][4];
        #pragma unroll
        for (int mt = 0; mt < 2; mt++)
            #pragma unroll
            for (int nt = 0; nt < 2; nt++)
                #pragma unroll
                for (int r = 0; r < 4; r++) sacc[mt][nt][r] = 0.f;

        #pragma unroll
        for (int ks = 0; ks < 8; ks++) {
            const int j0 = ks * 8;
            uint32_t ah[2][4], al[2][4], bhv[2][2], blv[2][2];
            #pragma unroll
            for (int mt = 0; mt < 2; mt++) {
                const int r = wr * 32 + mt * 16;
                const uint32_t base = (r + tr + row_off) * 68 + j0 + col_off;
                uint32_t r0, r1, r2, r3;
                LDSM_X4(r0, r1, r2, r3, sbase + (FL_QH + base) * 4);
                ah[mt][0] = r0; ah[mt][1] = r2; ah[mt][2] = r1; ah[mt][3] = r3;
                LDSM_X4(r0, r1, r2, r3, sbase + (FL_QL + base) * 4);
                al[mt][0] = r0; al[mt][1] = r2; al[mt][2] = r1; al[mt][3] = r3;
            }
            {
                const int c0 = wc * 16;
                const uint32_t base = (c0 + tr + row_off) * 68 + j0 + col_off;
                uint32_t r0, r1, r2, r3;
                LDSM_X4(r0, r1, r2, r3, sbase + (FL_KH + base) * 4);
                bhv[0][0] = r0; bhv[0][1] = r1; bhv[1][0] = r2; bhv[1][1] = r3;
                LDSM_X4(r0, r1, r2, r3, sbase + (FL_KL + base) * 4);
                blv[0][0] = r0; blv[0][1] = r1; blv[1][0] = r2; blv[1][1] = r3;
            }
            #pragma unroll
            for (int mt = 0; mt < 2; mt++)
                #pragma unroll
                for (int nt = 0; nt < 2; nt++) {
                    mma_bf16(sacc[mt][nt], ah[mt], bhv[nt]);
                    mma_bf16(sacc[mt][nt], ah[mt], blv[nt]);
                    mma_bf16(sacc[mt][nt], al[mt], bhv[nt]);
                }
        }

        // ---- scale + causal mask + stage to SF ----
        const bool maskt = (kt >= ntiles - 2);
        #pragma unroll
        for (int mt = 0; mt < 2; mt++) {
            const int r = wr * 32 + mt * 16 + gp;
            const int qp0 = HIST + q0 + r, qp1 = qp0 + 8;
            #pragma unroll
            for (int nt = 0; nt < 2; nt++) {
                const int cc = wc * 16 + nt * 8 + 2 * q;
                float v0 = sacc[mt][nt][0] * ATT_SCALE;
                float v1 = sacc[mt][nt][1] * ATT_SCALE;
                float v2 = sacc[mt][nt][2] * ATT_SCALE;
                float v3 = sacc[mt][nt][3] * ATT_SCALE;
                if (maskt) {
                    const int s_abs = s0 + cc;
                    if (s_abs     > qp0) v0 = -1e30f;
                    if (s_abs + 1 > qp0) v1 = -1e30f;
                    if (s_abs     > qp1) v2 = -1e30f;
                    if (s_abs + 1 > qp1) v3 = -1e30f;
                }
                SF[r * 68 + cc] = v0;       SF[r * 68 + cc + 1] = v1;
                SF[(r + 8) * 68 + cc] = v2; SF[(r + 8) * 68 + cc + 1] = v3;
            }
        }
        __syncthreads();    // K[kt] fully consumed; SF staged

        // prefetch next K tile: hides behind softmax + PV + loop turn
        if (more) issue_K(s0 + 64);

        // ---- online softmax (4 threads/row), write P bf16 hi/lo ----
        {
            const int row = tid >> 2, q2 = tid & 3;
            const float* prow = SF + row * 68 + q2 * 16;
            float pv[16];
            float mx = -1e30f;
            #pragma unroll
            for (int k = 0; k < 16; k++) { pv[k] = prow[k]; mx = fmaxf(mx, pv[k]); }
            mx = fmaxf(mx, __shfl_xor_sync(0xffffffffu, mx, 1));
            mx = fmaxf(mx, __shfl_xor_sync(0xffffffffu, mx, 2));
            const float m_old = m_s[row];
            const float m_new = fmaxf(m_old, mx);
            float ssum = 0.f;
            #pragma unroll
            for (int k = 0; k < 16; k++) {
                pv[k] = fast_exp(pv[k] - m_new);
                ssum += pv[k];
            }
            #pragma unroll
            for (int u = 0; u < 8; u++) {
                __nv_bfloat16 h0, l0, h1, l1;
                split_bf16(pv[2*u],   h0, l0);
                split_bf16(pv[2*u+1], h1, l1);
                PH[row * 36 + q2 * 8 + u] = pack2(h0, h1);
                PL[row * 36 + q2 * 8 + u] = pack2(l0, l1);
            }
            ssum += __shfl_xor_sync(0xffffffffu, ssum, 1);
            ssum += __shfl_xor_sync(0xffffffffu, ssum, 2);
            if (q2 == 0) {
                const float corr = fast_exp(m_old - m_new);
                l_s[row] = l_s[row] * corr + ssum;
                m_s[row] = m_new;
                c_s[row] = corr;
            }
        }

        // V[kt] ready (K[kt+1] may still be in flight when it exists)
        if (more) CP_WAIT(1); else CP_WAIT(0);
        __syncthreads();

        // ---- O = O*corr + P @ V  (bf16x3, ldmatrix) ----
        {
            const float c0 = c_s[wor * 16 + gp];
            const float c1 = c_s[wor * 16 + gp + 8];
            #pragma unroll
            for (int nt = 0; nt < 8; nt++) {
                oacc[nt][0] *= c0; oacc[nt][1] *= c0;
                oacc[nt][2] *= c1; oacc[nt][3] *= c1;
            }
        }
        #pragma unroll
        for (int js = 0; js < 4; js++) {
            const int j0 = js * 8;
            const int r = wor * 16;
            uint32_t ph[4], pl[4];
            {
                const uint32_t base = (r + tr + row_off) * 36 + j0 + col_off;
                uint32_t r0, r1, r2, r3;
                LDSM_X4(r0, r1, r2, r3, sbase + (FL_PH + base) * 4);
                ph[0] = r0; ph[1] = r2; ph[2] = r1; ph[3] = r3;
                LDSM_X4(r0, r1, r2, r3, sbase + (FL_PL + base) * 4);
                pl[0] = r0; pl[1] = r2; pl[2] = r1; pl[3] = r3;
            }
            #pragma unroll
            for (int pp = 0; pp < 4; pp++) {
                const int cu = woc * 32 + pp * 8;   // u32 col of V tile
                const uint32_t base = (js * 16 + tr + row_off_t) * 68 + cu + col_off_t;
                uint32_t r0, r1, r2, r3;
                uint32_t bvh[2][2], bvl[2][2];
                LDSM_X4_T(r0, r1, r2, r3, sbase + (FL_VH + base) * 4);
                bvh[0][0] = r0; bvh[0][1] = r1; bvh[1][0] = r2; bvh[1][1] = r3;
                LDSM_X4_T(r0, r1, r2, r3, sbase + (FL_VL + base) * 4);
                bvl[0][0] = r0; bvl[0][1] = r1; bvl[1][0] = r2; bvl[1][1] = r3;
                #pragma unroll
                for (int x = 0; x < 2; x++) {
                    const int nt = pp * 2 + x;
                    mma_bf16(oacc[nt], ph, bvh[x]);
                    mma_bf16(oacc[nt], ph, bvl[x]);
                    mma_bf16(oacc[nt], pl, bvh[x]);
                }
            }
        }
        __syncthreads();    // V[kt] fully consumed

        // prefetch next V tile: hides behind loop turn + next S-phase
        if (more) issue_V(s0 + 64);
    }

    // ---- epilogue (tf32-rounded: feeds GEMM2's A operand directly) ----
    {
        const int r = wor * 16 + gp;
        const float inv0 = 1.f / l_s[r];
        const float inv1 = 1.f / l_s[r + 8];
        const int t0 = b * SQ + q0 + r;
        #pragma unroll
        for (int nt = 0; nt < 8; nt++) {
            const int c = woc * 64 + nt * 8 + 2 * q;
            uint2 w0, w1;
            w0.x = f2tf32(oacc[nt][0] * inv0); w0.y = f2tf32(oacc[nt][1] * inv0);
            w1.x = f2tf32(oacc[nt][2] * inv1); w1.y = f2tf32(oacc[nt][3] * inv1);
            *(uint2*)&Og[(size_t)t0 * D_MODEL + h * DHEAD + c]       = w0;
            *(uint2*)&Og[(size_t)(t0 + 8) * D_MODEL + h * DHEAD + c] = w1;
        }
    }
}

// =====================================================================
// launch
// =====================================================================
extern "C" void kernel_launch(void* const* d_in, const int* in_sizes, int n_in,
                              void* d_out, int out_size)
{
    const float* hidden  = (const float*)d_in[0];
    const float* w_qkv   = (const float*)d_in[1];
    const float* b_qkv   = (const float*)d_in[2];
    const float* w_proj  = (const float*)d_in[3];
    const float* cosT    = (const float*)d_in[4];
    const float* sinT    = (const float*)d_in[5];
    const float* kcache  = (const float*)d_in[6];
    const float* vcache  = (const float*)d_in[7];
    const int*   blkOff  = (const int*)d_in[8];
    float* out = (float*)d_out;

    float *qkv_p, *attn_p, *hidR, *wqkvT, *wprojT;
    __nv_bfloat16 *kh, *kl, *vh, *vl;
    cudaGetSymbolAddress((void**)&qkv_p,  g_qkv);
    cudaGetSymbolAddress((void**)&attn_p, g_attn);
    cudaGetSymbolAddress((void**)&hidR,   g_hidR);
    cudaGetSymbolAddress((void**)&wqkvT,  g_wqkvT);
    cudaGetSymbolAddress((void**)&wprojT, g_wprojT);
    cudaGetSymbolAddress((void**)&kh, g_kh);
    cudaGetSymbolAddress((void**)&kl, g_kl);
    cudaGetSymbolAddress((void**)&vh, g_vh);
    cudaGetSymbolAddress((void**)&vl, g_vl);

    cudaFuncSetAttribute(tf32_gemm_cp_kernel,
                         cudaFuncAttributeMaxDynamicSharedMemorySize, G_SMEM_BYTES);
    cudaFuncSetAttribute(flash_v4_kernel,
                         cudaFuncAttributeMaxDynamicSharedMemorySize, FL_SMEM_BYTES);

    // 0) prep: transpose+round weights, round hidden
    transpose_tf32_kernel<<<dim3(3 * D_MODEL / 32, D_MODEL / 32), dim3(32, 8)>>>(
        w_qkv, wqkvT, D_MODEL, 3 * D_MODEL);
    transpose_tf32_kernel<<<dim3(D_MODEL / 32, D_MODEL / 32), dim3(32, 8)>>>(
        w_proj, wprojT, D_MODEL, D_MODEL);
    round_tf32_kernel<<<T_TOK * D_MODEL / 1024, 256>>>(hidden, hidR);

    // 1) QKV projection (swizzled rasterization)
    tf32_gemm_cp_kernel<<<dim3(3 * D_MODEL / 128, T_TOK / 128), 256, G_SMEM_BYTES>>>(
        hidR, wqkvT, b_qkv, qkv_p, T_TOK, 3 * D_MODEL, D_MODEL);

    // 2) build bf16-split K/V (cache gather + RoPE on new K)
    build_kv_kernel<<<dim3(SKV, B_SEQ), 128>>>(
        qkv_p, kcache, vcache, blkOff, cosT, sinT, kh, kl, vh, vl);

    // 3) causal flash attention (grid transposed: q-tiles fastest)
    flash_v4_kernel<<<dim3(SQ / 128, B_SEQ * H_HEADS), 512, FL_SMEM_BYTES>>>(
        qkv_p, kh, kl, vh, vl, cosT, sinT, attn_p);

    // 4) output projection (swizzled rasterization)
    tf32_gemm_cp_kernel<<<dim3(D_MODEL / 128, T_TOK / 128), 256, G_SMEM_BYTES>>>(
        attn_p, wprojT, nullptr, out, T_TOK, D_MODEL, D_MODEL);
}

// round 16
// speedup vs baseline: 1.0119x; 1.0119x over previous
#include <cuda_runtime.h>
#include <cuda_bf16.h>
#include <cstdint>

// ---------------- problem geometry ----------------
#define T_TOK   4096
#define D_MODEL 4096
#define H_HEADS 32
#define DHEAD   128
#define B_SEQ   4
#define SQ      1024
#define HIST    1024
#define SKV     2048
#define NBLK    32
#define BS_PAGE 64
#define ATT_SCALE  0.08838834764831845f
#define INV_LN1024 0.14426950408889634f

// ---------------- scratch ----------------
__device__ float g_qkv[50331648];            // [T, 3*D]
__device__ float g_attn[16777216];           // [T, D] (tf32-rounded by flash)
__device__ float g_hidR[16777216];           // [T, D] tf32-rounded hidden
__device__ float g_wqkvT[50331648];          // [3D, D] tf32-rounded, transposed
__device__ float g_wprojT[16777216];         // [D, D]
__device__ __nv_bfloat16 g_kh[33554432];     // [B,H,SKV,DH] hi
__device__ __nv_bfloat16 g_kl[33554432];     // lo
__device__ __nv_bfloat16 g_vh[33554432];
__device__ __nv_bfloat16 g_vl[33554432];

// ---------------- helpers ----------------
__device__ __forceinline__ uint32_t smem_u32(const void* p) {
    uint32_t a;
    asm("{ .reg .u64 t; cvta.to.shared.u64 t, %1; cvt.u32.u64 %0, t; }"
        : "=r"(a) : "l"(p));
    return a;
}
__device__ __forceinline__ uint32_t f2tf32(float f) {
    uint32_t u;
    asm("cvt.rna.tf32.f32 %0, %1;" : "=r"(u) : "f"(f));
    return u;
}
__device__ __forceinline__ uint32_t pack2(__nv_bfloat16 a, __nv_bfloat16 b) {
    __nv_bfloat162 t = __nv_bfloat162(a, b);   // a -> low 16 bits (k even)
    return *reinterpret_cast<uint32_t*>(&t);
}
__device__ __forceinline__ void split_bf16(float f, __nv_bfloat16& h, __nv_bfloat16& l) {
    h = __float2bfloat16(f);
    l = __float2bfloat16(f - __bfloat162float(h));
}
#define CP_ASYNC16(dst, src) \
    asm volatile("cp.async.ca.shared.global [%0], [%1], 16;" \
                 :: "r"(dst), "l"(src) : "memory")
#define CP_COMMIT() asm volatile("cp.async.commit_group;" ::: "memory")
#define CP_WAIT(n)  asm volatile("cp.async.wait_group %0;" :: "n"(n) : "memory")
#define LDSM_X4(R0,R1,R2,R3,A) \
    asm volatile("ldmatrix.sync.aligned.m8n8.x4.shared.b16 {%0,%1,%2,%3}, [%4];" \
                 : "=r"(R0), "=r"(R1), "=r"(R2), "=r"(R3) : "r"(A))
#define LDSM_X4_T(R0,R1,R2,R3,A) \
    asm volatile("ldmatrix.sync.aligned.m8n8.x4.trans.shared.b16 {%0,%1,%2,%3}, [%4];" \
                 : "=r"(R0), "=r"(R1), "=r"(R2), "=r"(R3) : "r"(A))
__device__ __forceinline__ void mma_bf16(float* c, const uint32_t* a, const uint32_t* b) {
    asm volatile(
        "mma.sync.aligned.m16n8k16.row.col.f32.bf16.bf16.f32 "
        "{%0,%1,%2,%3}, {%4,%5,%6,%7}, {%8,%9}, {%0,%1,%2,%3};"
        : "+f"(c[0]), "+f"(c[1]), "+f"(c[2]), "+f"(c[3])
        : "r"(a[0]), "r"(a[1]), "r"(a[2]), "r"(a[3]), "r"(b[0]), "r"(b[1]));
}
__device__ __forceinline__ void mma_tf32(float* c, const uint32_t* a, const uint32_t* b) {
    asm volatile(
        "mma.sync.aligned.m16n8k8.row.col.f32.tf32.tf32.f32 "
        "{%0,%1,%2,%3}, {%4,%5,%6,%7}, {%8,%9}, {%0,%1,%2,%3};"
        : "+f"(c[0]), "+f"(c[1]), "+f"(c[2]), "+f"(c[3])
        : "r"(a[0]), "r"(a[1]), "r"(a[2]), "r"(a[3]), "r"(b[0]), "r"(b[1]));
}
// exp(x) for x <= 0, FMA-pipe only. ~1e-7 rel err.
__device__ __forceinline__ float fast_exp(float x) {
    float y = fmaxf(x * 1.4426950408889634f, -126.f);
    float z = __fadd_rn(y, 12582912.f);
    int   n = __float_as_int(z) - 0x4B400000;
    float f = y - __fsub_rn(z, 12582912.f);
    float t = f * 0.6931471805599453f;
    float p = __fmaf_rn(t, 0.0013888889f, 0.0083333333f);
    p = __fmaf_rn(t, p, 0.0416666667f);
    p = __fmaf_rn(t, p, 0.1666666667f);
    p = __fmaf_rn(t, p, 0.5f);
    p = __fmaf_rn(t, p, 1.0f);
    p = __fmaf_rn(t, p, 1.0f);
    return p * __int_as_float((n + 127) << 23);
}

// =====================================================================
// Prep: W[K][N] fp32 -> WT[N][K] fp32 with tf32(RNA) rounding applied.
// =====================================================================
__global__ __launch_bounds__(256) void transpose_tf32_kernel(
    const float* __restrict__ W, float* __restrict__ WT, int Kd, int Nd)
{
    __shared__ float ts[32][33];
    const int n0 = blockIdx.x * 32, k0 = blockIdx.y * 32;
    const int tx = threadIdx.x, ty = threadIdx.y;
    #pragma unroll
    for (int j = ty; j < 32; j += 8)
        ts[j][tx] = W[(size_t)(k0 + j) * Nd + n0 + tx];
    __syncthreads();
    #pragma unroll
    for (int j = ty; j < 32; j += 8)
        WT[(size_t)(n0 + j) * Kd + k0 + tx] = __uint_as_float(f2tf32(ts[tx][j]));
}

// =====================================================================
// Prep: elementwise tf32(RNA) round.
// =====================================================================
__global__ __launch_bounds__(256) void round_tf32_kernel(
    const float* __restrict__ X, float* __restrict__ Y)
{
    const int i = (blockIdx.x * 256 + threadIdx.x) * 4;
    const float4 v = *(const float4*)(X + i);
    uint4 u;
    u.x = f2tf32(v.x); u.y = f2tf32(v.y); u.z = f2tf32(v.z); u.w = f2tf32(v.w);
    *(uint4*)(Y + i) = u;
}

// =====================================================================
// TF32 GEMM, cp.async double-buffered + CTA swizzle (exact R13).
// =====================================================================
#define G_SMEM_BYTES (18432 * 4)

__global__ __launch_bounds__(256, 2) void tf32_gemm_cp_kernel(
    const float* __restrict__ A, const float* __restrict__ BT,
    const float* __restrict__ bias, float* __restrict__ C,
    int M, int N, int K)
{
    extern __shared__ uint32_t sg[];
    const uint32_t sbase = smem_u32(sg);

    const int tid  = threadIdx.x;
    const int lin  = blockIdx.y * gridDim.x + blockIdx.x;
    const int grpW = 8 * gridDim.y;
    const int grp  = lin / grpW;
    const int rem  = lin - grp * grpW;
    const int bcol = grp * 8 + (rem & 7);
    const int brow = rem >> 3;

    const int warp = tid >> 5, lane = tid & 31;
    const int wr = warp >> 2, wc = warp & 3;
    const int gp = lane >> 2, q = lane & 3;
    const int tr = lane & 7, lg = lane >> 3;
    const int row_off = (lg & 2) ? 8 : 0;
    const int col_off = (lg & 1) ? 4 : 0;

    float acc[4][4][4];
    #pragma unroll
    for (int mt = 0; mt < 4; mt++)
        #pragma unroll
        for (int nt = 0; nt < 4; nt++)
            #pragma unroll
            for (int r = 0; r < 4; r++) acc[mt][nt][r] = 0.f;

    const float* Ab = A  + (size_t)(brow * 128) * K;
    const float* Bb = BT + (size_t)(bcol * 128) * K;

    const int fr = tid >> 3, fk = (tid & 7) << 2;

    auto fill = [&](int st, int kt) {
        const uint32_t aoff = sbase + (st * 4608) * 4;
        const uint32_t boff = sbase + ((9216 + st * 4608)) * 4;
        #pragma unroll
        for (int i = 0; i < 4; i++) {
            const int r = fr + 32 * i;
            const uint32_t d = (r * 36 + fk) * 4;
            CP_ASYNC16(aoff + d, Ab + (size_t)r * K + kt + fk);
            CP_ASYNC16(boff + d, Bb + (size_t)r * K + kt + fk);
        }
        CP_COMMIT();
    };

    fill(0, 0);

    for (int kt = 0; kt < K; kt += 32) {
        const int buf = (kt >> 5) & 1;
        const bool more = (kt + 32 < K);
        if (more) { fill(buf ^ 1, kt + 32); CP_WAIT(1); }
        else      { CP_WAIT(0); }
        __syncthreads();

        const uint32_t aoff = sbase + (buf * 4608) * 4;
        const uint32_t boff = sbase + ((9216 + buf * 4608)) * 4;
        #pragma unroll
        for (int kk = 0; kk < 32; kk += 8) {
            uint32_t af[4][4], bf[4][2];
            #pragma unroll
            for (int mt = 0; mt < 4; mt++) {
                const int r = wr * 64 + mt * 16;
                const uint32_t a = aoff + ((r + tr + row_off) * 36 + kk + col_off) * 4;
                uint32_t r0, r1, r2, r3;
                LDSM_X4(r0, r1, r2, r3, a);
                af[mt][0] = r0; af[mt][1] = r2; af[mt][2] = r1; af[mt][3] = r3;
            }
            #pragma unroll
            for (int pp = 0; pp < 2; pp++) {
                const int c0 = wc * 32 + pp * 16;
                const uint32_t a = boff + ((c0 + tr + row_off) * 36 + kk + col_off) * 4;
                uint32_t r0, r1, r2, r3;
                LDSM_X4(r0, r1, r2, r3, a);
                bf[2*pp][0]   = r0; bf[2*pp][1]   = r1;
                bf[2*pp+1][0] = r2; bf[2*pp+1][1] = r3;
            }
            #pragma unroll
            for (int mt = 0; mt < 4; mt++)
                #pragma unroll
                for (int nt = 0; nt < 4; nt++)
                    mma_tf32(acc[mt][nt], af[mt], bf[nt]);
        }
        __syncthreads();
    }

    #pragma unroll
    for (int mt = 0; mt < 4; mt++) {
        const int r0 = brow * 128 + wr * 64 + mt * 16 + gp;
        #pragma unroll
        for (int nt = 0; nt < 4; nt++) {
            const int c0 = bcol * 128 + wc * 32 + nt * 8 + 2 * q;
            float bb0 = 0.f, bb1 = 0.f;
            if (bias) { bb0 = bias[c0]; bb1 = bias[c0 + 1]; }
            float2 v0, v1;
            v0.x = acc[mt][nt][0] + bb0; v0.y = acc[mt][nt][1] + bb1;
            v1.x = acc[mt][nt][2] + bb0; v1.y = acc[mt][nt][3] + bb1;
            *(float2*)&C[(size_t)r0 * N + c0]       = v0;
            *(float2*)&C[(size_t)(r0 + 8) * N + c0] = v1;
        }
    }
}

// =====================================================================
// Build K/V as bf16 hi/lo, [B,H,SKV,DH].  grid (SKV, B), block 128.
// =====================================================================
__global__ void build_kv_kernel(const float* __restrict__ qkv,
                                const float* __restrict__ kcache,
                                const float* __restrict__ vcache,
                                const int* __restrict__ blockOff,
                                const float* __restrict__ cosT,
                                const float* __restrict__ sinT,
                                __nv_bfloat16* __restrict__ Kh,
                                __nv_bfloat16* __restrict__ Kl,
                                __nv_bfloat16* __restrict__ Vh,
                                __nv_bfloat16* __restrict__ Vl)
{
    const int s = blockIdx.x, b = blockIdx.y, d = threadIdx.x;
    if (s < HIST) {
        const int blk = blockOff[b * NBLK + (s >> 6)];
        const size_t src = ((size_t)(blk * BS_PAGE + (s & 63))) * H_HEADS * DHEAD;
        for (int h = 0; h < H_HEADS; h++) {
            const size_t dst = (((size_t)(b * H_HEADS + h)) * SKV + s) * DHEAD + d;
            __nv_bfloat16 hh, ll;
            split_bf16(kcache[src + h * DHEAD + d], hh, ll);
            Kh[dst] = hh; Kl[dst] = ll;
            split_bf16(vcache[src + h * DHEAD + d], hh, ll);
            Vh[dst] = hh; Vl[dst] = ll;
        }
    } else {
        const int t = b * SQ + (s - HIST);
        const int pos = s;
        const float c  = cosT[(size_t)pos * DHEAD + d];
        const float sn = sinT[(size_t)pos * DHEAD + d];
        const float* kp = qkv + (size_t)t * (3 * D_MODEL) + D_MODEL;
        const float* vp = kp + D_MODEL;
        for (int h = 0; h < H_HEADS; h++) {
            const float k1 = kp[h * DHEAD + d];
            const float rot = (d < 64) ? -kp[h * DHEAD + d + 64]
                                       :  kp[h * DHEAD + d - 64];
            const size_t dst = (((size_t)(b * H_HEADS + h)) * SKV + s) * DHEAD + d;
            __nv_bfloat16 hh, ll;
            split_bf16(k1 * c + rot * sn, hh, ll);
            Kh[dst] = hh; Kl[dst] = ll;
            split_bf16(vp[h * DHEAD + d], hh, ll);
            Vh[dst] = hh; Vl[dst] = ll;
        }
    }
}

// =====================================================================
// Flash attention v6: bf16x3 (R13 numerics), q-tile 64, s-tile 32,
// 256 threads, 90KB smem -> 2 CTAs/SM for cross-CTA latency hiding.
// smem (u32 offsets):
//   QH 0 [64][68]      QL 4352
//   KH 8704 [32][68]   KL 10880
//   VH 13056 [32][68]  VL 15232
//   SF 17408 [64][36] f32
//   PH 19712 [64][20]  PL 20992
//   ST 22272 (m/l/c 64 each)
// total 22464 u32 = 89856 B
// =====================================================================
#define FL_QH 0
#define FL_QL 4352
#define FL_KH 8704
#define FL_KL 10880
#define FL_VH 13056
#define FL_VL 15232
#define FL_SF 17408
#define FL_PH 19712
#define FL_PL 20992
#define FL_ST 22272
#define FL_SMEM_BYTES (22464 * 4)

__global__ __launch_bounds__(256, 2) void flash_v6_kernel(
    const float* __restrict__ Qg,
    const __nv_bfloat16* __restrict__ Kh,
    const __nv_bfloat16* __restrict__ Kl,
    const __nv_bfloat16* __restrict__ Vh,
    const __nv_bfloat16* __restrict__ Vl,
    const float* __restrict__ cosT,
    const float* __restrict__ sinT,
    float* __restrict__ Og)
{
    extern __shared__ uint32_t fsm[];
    uint32_t* QH = fsm + FL_QH;
    uint32_t* QL = fsm + FL_QL;
    float*    SF = (float*)(fsm + FL_SF);
    uint32_t* PH = fsm + FL_PH;
    uint32_t* PL = fsm + FL_PL;
    float* m_s = (float*)(fsm + FL_ST);
    float* l_s = m_s + 64;
    float* c_s = l_s + 64;
    const uint32_t sbase = smem_u32(fsm);

    const int bh = blockIdx.x;
    const int b = bh >> 5, h = bh & 31;
    const int q0 = blockIdx.y * 64;
    const int tid = threadIdx.x;
    const int warp = tid >> 5, lane = tid & 31;
    const int gp = lane >> 2, q = lane & 3;
    const int tr = lane & 7, lg = lane >> 3;
    const int wr = warp >> 1, wc = warp & 1;     // S phase: 4x2 (16 rows x 16 cols)
    const int wor = warp >> 1, woc = warp & 1;   // PV phase: 4x2 (16 rows x 64 cols)
    const int row_off = (lg & 2) ? 8 : 0;        // non-trans grouping
    const int col_off = (lg & 1) ? 4 : 0;
    const int row_off_t = (lg & 1) ? 8 : 0;      // trans grouping
    const int col_off_t = (lg & 2) ? 4 : 0;

    const size_t bhofs = (size_t)bh * SKV * DHEAD;
    const int ntiles = (HIST + q0 + 64) / 32;

    // per-thread fill coordinates (one 32-row tile = 8 cp.async per thread)
    const int frow = tid >> 3;                   // 0..31
    const int fc8  = (tid & 7) * 8;
    const uint32_t fdrow = (frow * 68 + fc8) * 4;

    auto issue_K = [&](int s0) {
        const size_t src = bhofs + (size_t)(s0 + frow) * DHEAD + fc8 * 2;
        CP_ASYNC16(sbase + (FL_KH) * 4 + fdrow,      Kh + src);
        CP_ASYNC16(sbase + (FL_KH + 4) * 4 + fdrow,  Kh + src + 8);
        CP_ASYNC16(sbase + (FL_KL) * 4 + fdrow,      Kl + src);
        CP_ASYNC16(sbase + (FL_KL + 4) * 4 + fdrow,  Kl + src + 8);
        CP_COMMIT();
    };
    auto issue_V = [&](int s0) {
        const size_t src = bhofs + (size_t)(s0 + frow) * DHEAD + fc8 * 2;
        CP_ASYNC16(sbase + (FL_VH) * 4 + fdrow,      Vh + src);
        CP_ASYNC16(sbase + (FL_VH + 4) * 4 + fdrow,  Vh + src + 8);
        CP_ASYNC16(sbase + (FL_VL) * 4 + fdrow,      Vl + src);
        CP_ASYNC16(sbase + (FL_VL + 4) * 4 + fdrow,  Vl + src + 8);
        CP_COMMIT();
    };

    issue_K(0);
    issue_V(0);

    // ---- load Q tile (64 rows) + RoPE + logn + bf16 split ----
    {
        const int row = tid >> 2;                // 0..63
        const int d0  = (tid & 3) * 16;
        const int t   = b * SQ + q0 + row;
        const int pos = HIST + q0 + row;
        const float logn = logf((float)(pos + 1)) * INV_LN1024;
        const float* qrow = Qg + (size_t)t * (3 * D_MODEL) + h * DHEAD;
        const float* crow = cosT + (size_t)pos * DHEAD;
        const float* srow = sinT + (size_t)pos * DHEAD;
        float qa[16], qb[16], ca[16], cb[16], sa[16], sb[16];
        #pragma unroll
        for (int i = 0; i < 4; i++) {
            *(float4*)&qa[4*i] = *(const float4*)(qrow + d0 + 4*i);
            *(float4*)&qb[4*i] = *(const float4*)(qrow + d0 + 64 + 4*i);
            *(float4*)&ca[4*i] = *(const float4*)(crow + d0 + 4*i);
            *(float4*)&cb[4*i] = *(const float4*)(crow + d0 + 64 + 4*i);
            *(float4*)&sa[4*i] = *(const float4*)(srow + d0 + 4*i);
            *(float4*)&sb[4*i] = *(const float4*)(srow + d0 + 64 + 4*i);
        }
        #pragma unroll
        for (int j = 0; j < 8; j++) {
            float f0 = (qa[2*j]   * ca[2*j]   - qb[2*j]   * sa[2*j])   * logn;
            float f1 = (qa[2*j+1] * ca[2*j+1] - qb[2*j+1] * sa[2*j+1]) * logn;
            float g0 = (qb[2*j]   * cb[2*j]   + qa[2*j]   * sb[2*j])   * logn;
            float g1 = (qb[2*j+1] * cb[2*j+1] + qa[2*j+1] * sb[2*j+1]) * logn;
            __nv_bfloat16 h0, l0, h1, l1;
            split_bf16(f0, h0, l0); split_bf16(f1, h1, l1);
            QH[row * 68 + d0/2 + j] = pack2(h0, h1);
            QL[row * 68 + d0/2 + j] = pack2(l0, l1);
            split_bf16(g0, h0, l0); split_bf16(g1, h1, l1);
            QH[row * 68 + (d0 + 64)/2 + j] = pack2(h0, h1);
            QL[row * 68 + (d0 + 64)/2 + j] = pack2(l0, l1);
        }
    }
    if (tid < 64) { m_s[tid] = -1e30f; l_s[tid] = 0.f; }

    float oacc[8][4];
    #pragma unroll
    for (int nt = 0; nt < 8; nt++)
        { oacc[nt][0]=0.f; oacc[nt][1]=0.f; oacc[nt][2]=0.f; oacc[nt][3]=0.f; }

    __syncthreads();

    for (int kt = 0; kt < ntiles; kt++) {
        const int s0 = kt * 32;
        const bool more = (kt + 1 < ntiles);

        // K[kt] ready (V[kt] may still be in flight)
        CP_WAIT(1);
        __syncthreads();

        // ---- S = Q @ K^T  (bf16x3, ldmatrix): warp = 16 rows x 16 cols ----
        float sacc[2][4];
        #pragma unroll
        for (int nt = 0; nt < 2; nt++)
            #pragma unroll
            for (int r = 0; r < 4; r++) sacc[nt][r] = 0.f;

        #pragma unroll
        for (int ks = 0; ks < 8; ks++) {
            const int j0 = ks * 8;
            uint32_t ah[4], al[4], bhv[2][2], blv[2][2];
            {
                const int r = wr * 16;
                const uint32_t base = (r + tr + row_off) * 68 + j0 + col_off;
                uint32_t r0, r1, r2, r3;
                LDSM_X4(r0, r1, r2, r3, sbase + (FL_QH + base) * 4);
                ah[0] = r0; ah[1] = r2; ah[2] = r1; ah[3] = r3;
                LDSM_X4(r0, r1, r2, r3, sbase + (FL_QL + base) * 4);
                al[0] = r0; al[1] = r2; al[2] = r1; al[3] = r3;
            }
            {
                const int c0 = wc * 16;
                const uint32_t base = (c0 + tr + row_off) * 68 + j0 + col_off;
                uint32_t r0, r1, r2, r3;
                LDSM_X4(r0, r1, r2, r3, sbase + (FL_KH + base) * 4);
                bhv[0][0] = r0; bhv[0][1] = r1; bhv[1][0] = r2; bhv[1][1] = r3;
                LDSM_X4(r0, r1, r2, r3, sbase + (FL_KL + base) * 4);
                blv[0][0] = r0; blv[0][1] = r1; blv[1][0] = r2; blv[1][1] = r3;
            }
            #pragma unroll
            for (int nt = 0; nt < 2; nt++) {
                mma_bf16(sacc[nt], ah, bhv[nt]);
                mma_bf16(sacc[nt], ah, blv[nt]);
                mma_bf16(sacc[nt], al, bhv[nt]);
            }
        }

        // ---- scale + causal mask + stage to SF ----
        const bool maskt = (kt >= ntiles - 2);
        {
            const int r = wr * 16 + gp;
            const int qp0 = HIST + q0 + r, qp1 = qp0 + 8;
            #pragma unroll
            for (int nt = 0; nt < 2; nt++) {
                const int cc = wc * 16 + nt * 8 + 2 * q;
                float v0 = sacc[nt][0] * ATT_SCALE;
                float v1 = sacc[nt][1] * ATT_SCALE;
                float v2 = sacc[nt][2] * ATT_SCALE;
                float v3 = sacc[nt][3] * ATT_SCALE;
                if (maskt) {
                    const int s_abs = s0 + cc;
                    if (s_abs     > qp0) v0 = -1e30f;
                    if (s_abs + 1 > qp0) v1 = -1e30f;
                    if (s_abs     > qp1) v2 = -1e30f;
                    if (s_abs + 1 > qp1) v3 = -1e30f;
                }
                SF[r * 36 + cc] = v0;       SF[r * 36 + cc + 1] = v1;
                SF[(r + 8) * 36 + cc] = v2; SF[(r + 8) * 36 + cc + 1] = v3;
            }
        }
        __syncthreads();    // K[kt] consumed; SF staged

        // prefetch next K tile
        if (more) issue_K(s0 + 32);

        // ---- online softmax (4 threads/row, 8 cols each), P bf16 hi/lo ----
        {
            const int row = tid >> 2, q2 = tid & 3;
            const float* prow = SF + row * 36 + q2 * 8;
            float pv[8];
            float mx = -1e30f;
            #pragma unroll
            for (int k = 0; k < 8; k++) { pv[k] = prow[k]; mx = fmaxf(mx, pv[k]); }
            mx = fmaxf(mx, __shfl_xor_sync(0xffffffffu, mx, 1));
            mx = fmaxf(mx, __shfl_xor_sync(0xffffffffu, mx, 2));
            const float m_old = m_s[row];
            const float m_new = fmaxf(m_old, mx);
            float ssum = 0.f;
            #pragma unroll
            for (int k = 0; k < 8; k++) {
                pv[k] = fast_exp(pv[k] - m_new);
                ssum += pv[k];
            }
            #pragma unroll
            for (int u = 0; u < 4; u++) {
                __nv_bfloat16 h0, l0, h1, l1;
                split_bf16(pv[2*u],   h0, l0);
                split_bf16(pv[2*u+1], h1, l1);
                PH[row * 20 + q2 * 4 + u] = pack2(h0, h1);
                PL[row * 20 + q2 * 4 + u] = pack2(l0, l1);
            }
            ssum += __shfl_xor_sync(0xffffffffu, ssum, 1);
            ssum += __shfl_xor_sync(0xffffffffu, ssum, 2);
            if (q2 == 0) {
                const float corr = fast_exp(m_old - m_new);
                l_s[row] = l_s[row] * corr + ssum;
                m_s[row] = m_new;
                c_s[row] = corr;
            }
        }

        // V[kt] ready
        if (more) CP_WAIT(1); else CP_WAIT(0);
        __syncthreads();

        // ---- O = O*corr + P @ V  (bf16x3, ldmatrix): warp = 16 rows x 64 cols ----
        {
            const float c0 = c_s[wor * 16 + gp];
            const float c1 = c_s[wor * 16 + gp + 8];
            #pragma unroll
            for (int nt = 0; nt < 8; nt++) {
                oacc[nt][0] *= c0; oacc[nt][1] *= c0;
                oacc[nt][2] *= c1; oacc[nt][3] *= c1;
            }
        }
        #pragma unroll
        for (int js = 0; js < 2; js++) {        // k = 32 s = 2 x k16
            const int j0 = js * 8;
            const int r = wor * 16;
            uint32_t ph[4], pl[4];
            {
                const uint32_t base = (r + tr + row_off) * 20 + j0 + col_off;
                uint32_t r0, r1, r2, r3;
                LDSM_X4(r0, r1, r2, r3, sbase + (FL_PH + base) * 4);
                ph[0] = r0; ph[1] = r2; ph[2] = r1; ph[3] = r3;
                LDSM_X4(r0, r1, r2, r3, sbase + (FL_PL + base) * 4);
                pl[0] = r0; pl[1] = r2; pl[2] = r1; pl[3] = r3;
            }
            #pragma unroll
            for (int pp = 0; pp < 4; pp++) {
                const int cu = woc * 32 + pp * 8;   // u32 col of V tile
                const uint32_t base = (js * 16 + tr + row_off_t) * 68 + cu + col_off_t;
                uint32_t r0, r1, r2, r3;
                uint32_t bvh[2][2], bvl[2][2];
                LDSM_X4_T(r0, r1, r2, r3, sbase + (FL_VH + base) * 4);
                bvh[0][0] = r0; bvh[0][1] = r1; bvh[1][0] = r2; bvh[1][1] = r3;
                LDSM_X4_T(r0, r1, r2, r3, sbase + (FL_VL + base) * 4);
                bvl[0][0] = r0; bvl[0][1] = r1; bvl[1][0] = r2; bvl[1][1] = r3;
                #pragma unroll
                for (int x = 0; x < 2; x++) {
                    const int nt = pp * 2 + x;
                    mma_bf16(oacc[nt], ph, bvh[x]);
                    mma_bf16(oacc[nt], ph, bvl[x]);
                    mma_bf16(oacc[nt], pl, bvh[x]);
                }
            }
        }
        __syncthreads();    // V[kt] consumed

        // prefetch next V tile
        if (more) issue_V(s0 + 32);
    }

    // ---- epilogue (tf32-rounded: feeds GEMM2's A operand directly) ----
    {
        const int r = wor * 16 + gp;
        const float inv0 = 1.f / l_s[r];
        const float inv1 = 1.f / l_s[r + 8];
        const int t0 = b * SQ + q0 + r;
        #pragma unroll
        for (int nt = 0; nt < 8; nt++) {
            const int c = woc * 64 + nt * 8 + 2 * q;
            uint2 w0, w1;
            w0.x = f2tf32(oacc[nt][0] * inv0); w0.y = f2tf32(oacc[nt][1] * inv0);
            w1.x = f2tf32(oacc[nt][2] * inv1); w1.y = f2tf32(oacc[nt][3] * inv1);
            *(uint2*)&Og[(size_t)t0 * D_MODEL + h * DHEAD + c]       = w0;
            *(uint2*)&Og[(size_t)(t0 + 8) * D_MODEL + h * DHEAD + c] = w1;
        }
    }
}

// =====================================================================
// launch
// =====================================================================
extern "C" void kernel_launch(void* const* d_in, const int* in_sizes, int n_in,
                              void* d_out, int out_size)
{
    const float* hidden  = (const float*)d_in[0];
    const float* w_qkv   = (const float*)d_in[1];
    const float* b_qkv   = (const float*)d_in[2];
    const float* w_proj  = (const float*)d_in[3];
    const float* cosT    = (const float*)d_in[4];
    const float* sinT    = (const float*)d_in[5];
    const float* kcache  = (const float*)d_in[6];
    const float* vcache  = (const float*)d_in[7];
    const int*   blkOff  = (const int*)d_in[8];
    float* out = (float*)d_out;

    float *qkv_p, *attn_p, *hidR, *wqkvT, *wprojT;
    __nv_bfloat16 *kh, *kl, *vh, *vl;
    cudaGetSymbolAddress((void**)&qkv_p,  g_qkv);
    cudaGetSymbolAddress((void**)&attn_p, g_attn);
    cudaGetSymbolAddress((void**)&hidR,   g_hidR);
    cudaGetSymbolAddress((void**)&wqkvT,  g_wqkvT);
    cudaGetSymbolAddress((void**)&wprojT, g_wprojT);
    cudaGetSymbolAddress((void**)&kh, g_kh);
    cudaGetSymbolAddress((void**)&kl, g_kl);
    cudaGetSymbolAddress((void**)&vh, g_vh);
    cudaGetSymbolAddress((void**)&vl, g_vl);

    cudaFuncSetAttribute(tf32_gemm_cp_kernel,
                         cudaFuncAttributeMaxDynamicSharedMemorySize, G_SMEM_BYTES);
    cudaFuncSetAttribute(flash_v6_kernel,
                         cudaFuncAttributeMaxDynamicSharedMemorySize, FL_SMEM_BYTES);

    // 0) prep: transpose+round weights, round hidden
    transpose_tf32_kernel<<<dim3(3 * D_MODEL / 32, D_MODEL / 32), dim3(32, 8)>>>(
        w_qkv, wqkvT, D_MODEL, 3 * D_MODEL);
    transpose_tf32_kernel<<<dim3(D_MODEL / 32, D_MODEL / 32), dim3(32, 8)>>>(
        w_proj, wprojT, D_MODEL, D_MODEL);
    round_tf32_kernel<<<T_TOK * D_MODEL / 1024, 256>>>(hidden, hidR);

    // 1) QKV projection (swizzled rasterization)
    tf32_gemm_cp_kernel<<<dim3(3 * D_MODEL / 128, T_TOK / 128), 256, G_SMEM_BYTES>>>(
        hidR, wqkvT, b_qkv, qkv_p, T_TOK, 3 * D_MODEL, D_MODEL);

    // 2) build bf16-split K/V (cache gather + RoPE on new K)
    build_kv_kernel<<<dim3(SKV, B_SEQ), 128>>>(
        qkv_p, kcache, vcache, blkOff, cosT, sinT, kh, kl, vh, vl);

    // 3) causal flash attention (q64/s32 tiles, 2 CTAs/SM)
    flash_v6_kernel<<<dim3(B_SEQ * H_HEADS, SQ / 64), 256, FL_SMEM_BYTES>>>(
        qkv_p, kh, kl, vh, vl, cosT, sinT, attn_p);

    // 4) output projection (swizzled rasterization)
    tf32_gemm_cp_kernel<<<dim3(D_MODEL / 128, T_TOK / 128), 256, G_SMEM_BYTES>>>(
        attn_p, wprojT, nullptr, out, T_TOK, D_MODEL, D_MODEL);
}